// round 7
// baseline (speedup 1.0000x reference)
#include <cuda_runtime.h>
#include <cstdint>

#define NROWS 50000
#define DIM   128
#define FILT  128
#define RB    20
#define P_EDGES 1600000

// scratch (device globals: no allocation allowed)
__device__ float g_h[NROWS * FILT];
__device__ float g_agg[NROWS * FILT];
__device__ float g_WinT[DIM * FILT];   // [k=d][oc=f]
__device__ float g_WoutT[FILT * DIM];  // [k=f][oc=d]
__device__ int4  g_meta[P_EDGES];      // (idx_i, idx_j, bitcast(rcut), 0)

__device__ __forceinline__ float sspf(float x) {
    // softplus(x) - ln2, fast path. For x>15, log1p(exp(x)) ~= x (err < 3e-7)
    float r = __logf(1.0f + __expf(x));
    r = (x > 15.0f) ? x : r;
    return r - 0.69314718055994530942f;
}

// packed f32x2 helpers
#define PACK2(d, lo, hi) asm("mov.b64 %0, {%1, %2};" : "=l"(d) : "f"(lo), "f"(hi))
#define UNPACK2(lo, hi, s) asm("mov.b64 {%0, %1}, %2;" : "=f"(lo), "=f"(hi) : "l"(s))
#define FMA2(acc, a, b) asm("fma.rn.f32x2 %0, %1, %2, %0;" : "+l"(acc) : "l"(a), "l"(b))

union F4U { float4 f; unsigned long long u[2]; };

// ---------------------------------------------------------------------------
// transpose both 128x128 weight matrices into [k][oc] layout
// ---------------------------------------------------------------------------
__global__ void transpose2_kernel(const float* __restrict__ Win,
                                  const float* __restrict__ Wout) {
    int i = blockIdx.x * blockDim.x + threadIdx.x;
    if (i < 128 * 128) {
        int oc = i >> 7, k = i & 127;
        g_WinT[k * 128 + oc]  = Win[oc * 128 + k];
        g_WoutT[k * 128 + oc] = Wout[oc * 128 + k];
    }
}

__global__ void zero_agg_kernel() {
    int i = blockIdx.x * blockDim.x + threadIdx.x;
    int stride = gridDim.x * blockDim.x;
    float4 z = make_float4(0.f, 0.f, 0.f, 0.f);
    float4* p = reinterpret_cast<float4*>(g_agg);
    for (; i < NROWS * FILT / 4; i += stride) p[i] = z;
}

// pack (idx_i, idx_j, rcut) into one int4 per edge -> 1 LDG.128 in edge kernel
__global__ void pack_meta_kernel(const int* __restrict__ idx_i,
                                 const int* __restrict__ idx_j,
                                 const float* __restrict__ rc) {
    int i = blockIdx.x * blockDim.x + threadIdx.x;
    int stride = gridDim.x * blockDim.x;
    for (; i < P_EDGES; i += stride)
        g_meta[i] = make_int4(idx_i[i], idx_j[i], __float_as_int(rc[i]), 0);
}

// ---------------------------------------------------------------------------
// GEMM: C[n, oc] = act( sum_k A[n,k] * WT[k,oc] + bias[oc] )
// A: [nrows,128], WT: [128,128] (k-major). Block tile 64x128, thread tile 8x4.
// Inner product uses packed fma.rn.f32x2 (2 FMAs / instruction).
// ---------------------------------------------------------------------------
template <bool SSP>
__global__ __launch_bounds__(256) void gemm_kernel(const float* __restrict__ A,
                                                   const float* __restrict__ WT,
                                                   const float* __restrict__ bias,
                                                   float* __restrict__ C,
                                                   int nrows) {
    __shared__ float As[64][32];
    __shared__ float Ws[32][128];

    int tid  = threadIdx.x;
    int warp = tid >> 5;
    int lane = tid & 31;
    int gr0  = blockIdx.x * 64;
    int r0   = warp * 8;
    int c0   = lane * 4;

    unsigned long long acc[8][2];   // (cx,cy),(cz,cw) packed pairs per row
#pragma unroll
    for (int i = 0; i < 8; i++) { acc[i][0] = 0ULL; acc[i][1] = 0ULL; }

    for (int k0 = 0; k0 < 128; k0 += 32) {
        // stage A tile: 64 rows x 32 k = 512 float4
#pragma unroll
        for (int v = 0; v < 2; v++) {
            int fi  = tid + v * 256;   // 0..511
            int row = fi >> 3;
            int kq  = fi & 7;
            int grow = gr0 + row;
            float4 val = make_float4(0.f, 0.f, 0.f, 0.f);
            if (grow < nrows)
                val = *reinterpret_cast<const float4*>(A + (size_t)grow * 128 + k0 + kq * 4);
            *reinterpret_cast<float4*>(&As[row][kq * 4]) = val;
        }
        // stage W tile: 32 k x 128 oc = 1024 float4
#pragma unroll
        for (int v = 0; v < 4; v++) {
            int fi = tid + v * 256;    // 0..1023
            int kr = fi >> 5;
            int f4 = fi & 31;
            *reinterpret_cast<float4*>(&Ws[kr][f4 * 4]) =
                *reinterpret_cast<const float4*>(WT + (size_t)(k0 + kr) * 128 + f4 * 4);
        }
        __syncthreads();

#pragma unroll
        for (int kk = 0; kk < 32; kk++) {
            F4U bu;
            bu.f = *reinterpret_cast<const float4*>(&Ws[kk][c0]);
#pragma unroll
            for (int i = 0; i < 8; i++) {
                float a = As[r0 + i][kk];   // broadcast LDS
                unsigned long long ap;
                PACK2(ap, a, a);
                FMA2(acc[i][0], ap, bu.u[0]);
                FMA2(acc[i][1], ap, bu.u[1]);
            }
        }
        __syncthreads();
    }

    float4 bb = *reinterpret_cast<const float4*>(bias + c0);
#pragma unroll
    for (int i = 0; i < 8; i++) {
        int grow = gr0 + r0 + i;
        if (grow < nrows) {
            float4 o;
            UNPACK2(o.x, o.y, acc[i][0]);
            UNPACK2(o.z, o.w, acc[i][1]);
            o.x += bb.x; o.y += bb.y; o.z += bb.z; o.w += bb.w;
            if (SSP) {
                o.x = sspf(o.x); o.y = sspf(o.y);
                o.z = sspf(o.z); o.w = sspf(o.w);
            }
            *reinterpret_cast<float4*>(C + (size_t)grow * 128 + c0) = o;
        }
    }
}

// ---------------------------------------------------------------------------
// Edge kernel: one warp per edge (grid-stride), lane owns 4 consecutive filters.
// Filter weights register-resident, packed as f32x2 r-pairs; the f_ij row's
// r-pairs come free from the float4 load registers (no pack movs).
// acc lane layout: low = sum over even r (+bias), high = sum over odd r.
// ---------------------------------------------------------------------------
__global__ __launch_bounds__(256) void edge_kernel(const float* __restrict__ f_ij,
                                                   const float* __restrict__ W_filter,
                                                   const float* __restrict__ b_filter) {
    int lane  = threadIdx.x & 31;
    int gwarp = (blockIdx.x * blockDim.x + threadIdx.x) >> 5;
    int nwarp = (gridDim.x * blockDim.x) >> 5;
    int f0    = lane * 4;

    unsigned long long w2[4][10];   // w2[j][rp] = (W[f0+j][2rp], W[f0+j][2rp+1])
    float bb[4];
#pragma unroll
    for (int j = 0; j < 4; j++) {
        bb[j] = __ldg(b_filter + f0 + j);
        const float2* wr = reinterpret_cast<const float2*>(W_filter + (size_t)(f0 + j) * RB);
#pragma unroll
        for (int rp = 0; rp < 10; rp++) {
            float2 v = __ldg(wr + rp);
            PACK2(w2[j][rp], v.x, v.y);
        }
    }

    for (int p = gwarp; p < P_EDGES; p += nwarp) {
        int4 mt = __ldg(&g_meta[p]);
        int   ii = mt.x;
        int   ji = mt.y;
        float rc = __int_as_float(mt.z);

        F4U q[5];
        const float4* fr = reinterpret_cast<const float4*>(f_ij + (size_t)p * RB);
#pragma unroll
        for (int t = 0; t < 5; t++) q[t].f = __ldg(fr + t);

        unsigned long long acc[4];
#pragma unroll
        for (int j = 0; j < 4; j++) PACK2(acc[j], bb[j], 0.f);

#pragma unroll
        for (int rp = 0; rp < 10; rp++) {
            unsigned long long fp = q[rp >> 1].u[rp & 1];
#pragma unroll
            for (int j = 0; j < 4; j++) FMA2(acc[j], fp, w2[j][rp]);
        }

        float a[4];
#pragma unroll
        for (int j = 0; j < 4; j++) {
            float lo, hi;
            UNPACK2(lo, hi, acc[j]);
            a[j] = lo + hi;
        }

        float4 hv = *reinterpret_cast<const float4*>(g_h + (size_t)ji * FILT + f0);
        float ox = sspf(a[0]) * rc * hv.x;
        float oy = sspf(a[1]) * rc * hv.y;
        float oz = sspf(a[2]) * rc * hv.z;
        float ow = sspf(a[3]) * rc * hv.w;

        float* dst = g_agg + (size_t)ii * FILT + f0;
        asm volatile("red.global.add.v4.f32 [%0], {%1, %2, %3, %4};"
                     :: "l"(dst), "f"(ox), "f"(oy), "f"(oz), "f"(ow)
                     : "memory");
    }
}

// ---------------------------------------------------------------------------
extern "C" void kernel_launch(void* const* d_in, const int* in_sizes, int n_in,
                              void* d_out, int out_size) {
    int ix = -1, ifij = -1, iwf = -1;
    int i16k[4]; int n16k = 0;       // W_in, W_out (16384 elems each)
    int i1m6[4]; int n1m6 = 0;       // idx_i, idx_j, rcut_ij (1.6M each)
    int i128[4]; int n128 = 0;       // b_in, b_filter, b_out (128 each)

    for (int i = 0; i < n_in; i++) {
        long s = in_sizes[i];
        if      (s == 6400000)  ix   = i;              // x [1,50000,128]
        else if (s == 32000000) ifij = i;              // f_ij [P,20]
        else if (s == 2560)     iwf  = i;              // W_filter [128,20]
        else if (s == 16384)  { if (n16k < 4) i16k[n16k++] = i; }
        else if (s == 1600000){ if (n1m6 < 4) i1m6[n1m6++] = i; }
        else if (s == 128)    { if (n128 < 4) i128[n128++] = i; }
    }

    const float* x        = (const float*)d_in[ix];
    const float* f_ij     = (const float*)d_in[ifij];
    const float* W_filter = (const float*)d_in[iwf];
    const int*   idx_i    = (const int*)d_in[i1m6[0]];
    const int*   idx_j    = (const int*)d_in[i1m6[1]];
    const float* rcut_ij  = (const float*)d_in[i1m6[2]];
    const float* W_in     = (const float*)d_in[i16k[0]];
    const float* W_out    = (const float*)d_in[i16k[1]];
    bool sorted_keys = (i128[0] < ifij);
    const float* b_in     = (const float*)d_in[sorted_keys ? i128[1] : i128[0]];
    const float* b_filter = (const float*)d_in[sorted_keys ? i128[0] : i128[1]];
    const float* b_out    = (const float*)d_in[i128[2]];

    float* out = (float*)d_out;

    // Resolve REAL device addresses of scratch globals (host query, no alloc,
    // executes immediately — safe under graph capture).
    void *p_h, *p_agg, *p_WinT, *p_WoutT;
    cudaGetSymbolAddress(&p_h,     g_h);
    cudaGetSymbolAddress(&p_agg,   g_agg);
    cudaGetSymbolAddress(&p_WinT,  g_WinT);
    cudaGetSymbolAddress(&p_WoutT, g_WoutT);
    float* dev_h     = (float*)p_h;
    float* dev_agg   = (float*)p_agg;
    float* dev_WinT  = (float*)p_WinT;
    float* dev_WoutT = (float*)p_WoutT;

    // 1. transpose weights (k-major for GEMM) + pack edge metadata
    transpose2_kernel<<<64, 256>>>(W_in, W_out);
    pack_meta_kernel<<<1024, 256>>>(idx_i, idx_j, rcut_ij);

    // 2. h = x @ W_in^T + b_in
    gemm_kernel<false><<<(NROWS + 63) / 64, 256>>>(x, dev_WinT, b_in, dev_h, NROWS);

    // 3. zero accumulator
    zero_agg_kernel<<<1024, 256>>>();

    // 4. fused filter-net + gather + scatter-add (persistent grid, 2 CTA/SM)
    edge_kernel<<<592, 256>>>(f_ij, W_filter, b_filter);

    // 5. out = ssp(agg @ W_out^T + b_out)
    gemm_kernel<true><<<(NROWS + 63) / 64, 256>>>(dev_agg, dev_WoutT, b_out, out, NROWS);
}

// round 9
// speedup vs baseline: 1.2544x; 1.2544x over previous
#include <cuda_runtime.h>
#include <cstdint>

#define NROWS 50000
#define DIM   128
#define FILT  128
#define RB    20
#define P_EDGES 1600000

// scratch (device globals: no allocation allowed)
__device__ float g_h[NROWS * FILT];
__device__ float g_agg[NROWS * FILT];
__device__ float g_WinT[DIM * FILT];   // [k=d][oc=f]
__device__ float g_WoutT[FILT * DIM];  // [k=f][oc=d]
__device__ int4  g_meta[P_EDGES];      // (idx_i, idx_j, bitcast(rcut), 0)

__device__ __forceinline__ float sspf(float x) {
    // softplus(x) - ln2, fast path. For x>15, log1p(exp(x)) ~= x (err < 3e-7)
    float r = __logf(1.0f + __expf(x));
    r = (x > 15.0f) ? x : r;
    return r - 0.69314718055994530942f;
}

// packed f32x2 helpers
#define PACK2(d, lo, hi) asm("mov.b64 %0, {%1, %2};" : "=l"(d) : "f"(lo), "f"(hi))
#define UNPACK2(lo, hi, s) asm("mov.b64 {%0, %1}, %2;" : "=f"(lo), "=f"(hi) : "l"(s))
#define FMA2(acc, a, b) asm("fma.rn.f32x2 %0, %1, %2, %0;" : "+l"(acc) : "l"(a), "l"(b))

union F4U { float4 f; unsigned long long u[2]; };

// ---------------------------------------------------------------------------
// transpose both 128x128 weight matrices into [k][oc] layout
// ---------------------------------------------------------------------------
__global__ void transpose2_kernel(const float* __restrict__ Win,
                                  const float* __restrict__ Wout) {
    int i = blockIdx.x * blockDim.x + threadIdx.x;
    if (i < 128 * 128) {
        int oc = i >> 7, k = i & 127;
        g_WinT[k * 128 + oc]  = Win[oc * 128 + k];
        g_WoutT[k * 128 + oc] = Wout[oc * 128 + k];
    }
}

__global__ void zero_agg_kernel() {
    int i = blockIdx.x * blockDim.x + threadIdx.x;
    int stride = gridDim.x * blockDim.x;
    float4 z = make_float4(0.f, 0.f, 0.f, 0.f);
    float4* p = reinterpret_cast<float4*>(g_agg);
    for (; i < NROWS * FILT / 4; i += stride) p[i] = z;
}

// pack (idx_i, idx_j, rcut) into one int4 per edge -> 1 LDG.128 in edge kernel
__global__ void pack_meta_kernel(const int* __restrict__ idx_i,
                                 const int* __restrict__ idx_j,
                                 const float* __restrict__ rc) {
    int i = blockIdx.x * blockDim.x + threadIdx.x;
    int stride = gridDim.x * blockDim.x;
    for (; i < P_EDGES; i += stride)
        g_meta[i] = make_int4(idx_i[i], idx_j[i], __float_as_int(rc[i]), 0);
}

// ---------------------------------------------------------------------------
// GEMM (R6-proven scalar version): C[n,oc] = act(sum_k A[n,k]*WT[k,oc] + b[oc])
// A: [nrows,128], WT: [128,128] (k-major). Block tile 64x128, thread tile 8x4.
// ---------------------------------------------------------------------------
template <bool SSP>
__global__ __launch_bounds__(256) void gemm_kernel(const float* __restrict__ A,
                                                   const float* __restrict__ WT,
                                                   const float* __restrict__ bias,
                                                   float* __restrict__ C,
                                                   int nrows) {
    __shared__ float As[64][32];
    __shared__ float Ws[32][128];

    int tid  = threadIdx.x;
    int warp = tid >> 5;
    int lane = tid & 31;
    int gr0  = blockIdx.x * 64;
    int r0   = warp * 8;
    int c0   = lane * 4;

    float4 acc[8];
#pragma unroll
    for (int i = 0; i < 8; i++) acc[i] = make_float4(0.f, 0.f, 0.f, 0.f);

    for (int k0 = 0; k0 < 128; k0 += 32) {
#pragma unroll
        for (int v = 0; v < 2; v++) {
            int fi  = tid + v * 256;   // 0..511
            int row = fi >> 3;
            int kq  = fi & 7;
            int grow = gr0 + row;
            float4 val = make_float4(0.f, 0.f, 0.f, 0.f);
            if (grow < nrows)
                val = *reinterpret_cast<const float4*>(A + (size_t)grow * 128 + k0 + kq * 4);
            *reinterpret_cast<float4*>(&As[row][kq * 4]) = val;
        }
#pragma unroll
        for (int v = 0; v < 4; v++) {
            int fi = tid + v * 256;    // 0..1023
            int kr = fi >> 5;
            int f4 = fi & 31;
            *reinterpret_cast<float4*>(&Ws[kr][f4 * 4]) =
                *reinterpret_cast<const float4*>(WT + (size_t)(k0 + kr) * 128 + f4 * 4);
        }
        __syncthreads();

#pragma unroll
        for (int kk = 0; kk < 32; kk++) {
            float4 bv = *reinterpret_cast<const float4*>(&Ws[kk][c0]);
#pragma unroll
            for (int i = 0; i < 8; i++) {
                float a = As[r0 + i][kk];   // broadcast LDS
                acc[i].x = fmaf(a, bv.x, acc[i].x);
                acc[i].y = fmaf(a, bv.y, acc[i].y);
                acc[i].z = fmaf(a, bv.z, acc[i].z);
                acc[i].w = fmaf(a, bv.w, acc[i].w);
            }
        }
        __syncthreads();
    }

    float4 bb = *reinterpret_cast<const float4*>(bias + c0);
#pragma unroll
    for (int i = 0; i < 8; i++) {
        int grow = gr0 + r0 + i;
        if (grow < nrows) {
            float4 o;
            o.x = acc[i].x + bb.x;
            o.y = acc[i].y + bb.y;
            o.z = acc[i].z + bb.z;
            o.w = acc[i].w + bb.w;
            if (SSP) {
                o.x = sspf(o.x); o.y = sspf(o.y);
                o.z = sspf(o.z); o.w = sspf(o.w);
            }
            *reinterpret_cast<float4*>(C + (size_t)grow * 128 + c0) = o;
        }
    }
}

// ---------------------------------------------------------------------------
// Edge kernel: one warp per edge (grid-stride), lane owns 4 consecutive
// filters. Filter weights register-resident as packed f32x2 r-pairs (the f_ij
// r-pairs come free from the float4 load register quads). launch_bounds
// (256, 2) FORCES <=128 regs so occupancy stays at 2 CTAs/SM (the R7
// regression was this kernel silently exceeding 128 regs -> 1 CTA/SM).
// acc lane layout: low = sum over even r (+bias), high = sum over odd r.
// ---------------------------------------------------------------------------
__global__ __launch_bounds__(256, 2) void edge_kernel(const float* __restrict__ f_ij,
                                                      const float* __restrict__ W_filter,
                                                      const float* __restrict__ b_filter) {
    int lane  = threadIdx.x & 31;
    int gwarp = (blockIdx.x * blockDim.x + threadIdx.x) >> 5;
    int nwarp = (gridDim.x * blockDim.x) >> 5;
    int f0    = lane * 4;

    unsigned long long w2[4][10];   // w2[j][rp] = (W[f0+j][2rp], W[f0+j][2rp+1])
    unsigned long long bbp[4];      // (bias, 0) pre-packed
#pragma unroll
    for (int j = 0; j < 4; j++) {
        PACK2(bbp[j], __ldg(b_filter + f0 + j), 0.f);
        const float2* wr = reinterpret_cast<const float2*>(W_filter + (size_t)(f0 + j) * RB);
#pragma unroll
        for (int rp = 0; rp < 10; rp++) {
            float2 v = __ldg(wr + rp);
            PACK2(w2[j][rp], v.x, v.y);
        }
    }

    for (int p = gwarp; p < P_EDGES; p += nwarp) {
        int4 mt = __ldg(&g_meta[p]);
        int   ii = mt.x;
        int   ji = mt.y;
        float rc = __int_as_float(mt.z);

        F4U q[5];
        const float4* fr = reinterpret_cast<const float4*>(f_ij + (size_t)p * RB);
#pragma unroll
        for (int t = 0; t < 5; t++) q[t].f = __ldg(fr + t);

        unsigned long long acc[4];
#pragma unroll
        for (int j = 0; j < 4; j++) acc[j] = bbp[j];

#pragma unroll
        for (int rp = 0; rp < 10; rp++) {
            unsigned long long fp = q[rp >> 1].u[rp & 1];
#pragma unroll
            for (int j = 0; j < 4; j++) FMA2(acc[j], fp, w2[j][rp]);
        }

        float a[4];
#pragma unroll
        for (int j = 0; j < 4; j++) {
            float lo, hi;
            UNPACK2(lo, hi, acc[j]);
            a[j] = lo + hi;
        }

        float4 hv = *reinterpret_cast<const float4*>(g_h + (size_t)ji * FILT + f0);
        float ox = sspf(a[0]) * rc * hv.x;
        float oy = sspf(a[1]) * rc * hv.y;
        float oz = sspf(a[2]) * rc * hv.z;
        float ow = sspf(a[3]) * rc * hv.w;

        float* dst = g_agg + (size_t)ii * FILT + f0;
        asm volatile("red.global.add.v4.f32 [%0], {%1, %2, %3, %4};"
                     :: "l"(dst), "f"(ox), "f"(oy), "f"(oz), "f"(ow)
                     : "memory");
    }
}

// ---------------------------------------------------------------------------
extern "C" void kernel_launch(void* const* d_in, const int* in_sizes, int n_in,
                              void* d_out, int out_size) {
    int ix = -1, ifij = -1, iwf = -1;
    int i16k[4]; int n16k = 0;       // W_in, W_out (16384 elems each)
    int i1m6[4]; int n1m6 = 0;       // idx_i, idx_j, rcut_ij (1.6M each)
    int i128[4]; int n128 = 0;       // b_in, b_filter, b_out (128 each)

    for (int i = 0; i < n_in; i++) {
        long s = in_sizes[i];
        if      (s == 6400000)  ix   = i;              // x [1,50000,128]
        else if (s == 32000000) ifij = i;              // f_ij [P,20]
        else if (s == 2560)     iwf  = i;              // W_filter [128,20]
        else if (s == 16384)  { if (n16k < 4) i16k[n16k++] = i; }
        else if (s == 1600000){ if (n1m6 < 4) i1m6[n1m6++] = i; }
        else if (s == 128)    { if (n128 < 4) i128[n128++] = i; }
    }

    const float* x        = (const float*)d_in[ix];
    const float* f_ij     = (const float*)d_in[ifij];
    const float* W_filter = (const float*)d_in[iwf];
    const int*   idx_i    = (const int*)d_in[i1m6[0]];
    const int*   idx_j    = (const int*)d_in[i1m6[1]];
    const float* rcut_ij  = (const float*)d_in[i1m6[2]];
    const float* W_in     = (const float*)d_in[i16k[0]];
    const float* W_out    = (const float*)d_in[i16k[1]];
    bool sorted_keys = (i128[0] < ifij);
    const float* b_in     = (const float*)d_in[sorted_keys ? i128[1] : i128[0]];
    const float* b_filter = (const float*)d_in[sorted_keys ? i128[0] : i128[1]];
    const float* b_out    = (const float*)d_in[i128[2]];

    float* out = (float*)d_out;

    // Resolve REAL device addresses of scratch globals (host query, no alloc,
    // executes immediately — safe under graph capture).
    void *p_h, *p_agg, *p_WinT, *p_WoutT;
    cudaGetSymbolAddress(&p_h,     g_h);
    cudaGetSymbolAddress(&p_agg,   g_agg);
    cudaGetSymbolAddress(&p_WinT,  g_WinT);
    cudaGetSymbolAddress(&p_WoutT, g_WoutT);
    float* dev_h     = (float*)p_h;
    float* dev_agg   = (float*)p_agg;
    float* dev_WinT  = (float*)p_WinT;
    float* dev_WoutT = (float*)p_WoutT;

    // 1. transpose weights (k-major for GEMM) + pack edge metadata
    transpose2_kernel<<<64, 256>>>(W_in, W_out);
    pack_meta_kernel<<<1024, 256>>>(idx_i, idx_j, rcut_ij);

    // 2. h = x @ W_in^T + b_in
    gemm_kernel<false><<<(NROWS + 63) / 64, 256>>>(x, dev_WinT, b_in, dev_h, NROWS);

    // 3. zero accumulator
    zero_agg_kernel<<<1024, 256>>>();

    // 4. fused filter-net + gather + scatter-add (2 CTA/SM enforced)
    edge_kernel<<<1184, 256>>>(f_ij, W_filter, b_filter);

    // 5. out = ssp(agg @ W_out^T + b_out)
    gemm_kernel<true><<<(NROWS + 63) / 64, 256>>>(dev_agg, dev_WoutT, b_out, out, NROWS);
}

// round 10
// speedup vs baseline: 1.4155x; 1.1284x over previous
#include <cuda_runtime.h>
#include <cstdint>

#define NROWS 50000
#define DIM   128
#define FILT  128
#define RB    20
#define P_EDGES 1600000

// scratch (device globals: no allocation allowed)
__device__ float g_h[NROWS * FILT];
__device__ float g_agg[NROWS * FILT];
__device__ float g_WinT[DIM * FILT];   // [k=d][oc=f]
__device__ float g_WoutT[FILT * DIM];  // [k=f][oc=d]
__device__ int4  g_meta[P_EDGES];      // (idx_i, idx_j, bitcast(rcut), 0)

__device__ __forceinline__ float sspf(float x) {
    // softplus(x) - ln2, fast path. For x>15, log1p(exp(x)) ~= x (err < 3e-7)
    float r = __logf(1.0f + __expf(x));
    r = (x > 15.0f) ? x : r;
    return r - 0.69314718055994530942f;
}

// ---------------------------------------------------------------------------
// transpose both 128x128 weight matrices into [k][oc] layout
// ---------------------------------------------------------------------------
__global__ void transpose2_kernel(const float* __restrict__ Win,
                                  const float* __restrict__ Wout) {
    int i = blockIdx.x * blockDim.x + threadIdx.x;
    if (i < 128 * 128) {
        int oc = i >> 7, k = i & 127;
        g_WinT[k * 128 + oc]  = Win[oc * 128 + k];
        g_WoutT[k * 128 + oc] = Wout[oc * 128 + k];
    }
}

__global__ void zero_agg_kernel() {
    int i = blockIdx.x * blockDim.x + threadIdx.x;
    int stride = gridDim.x * blockDim.x;
    float4 z = make_float4(0.f, 0.f, 0.f, 0.f);
    float4* p = reinterpret_cast<float4*>(g_agg);
    for (; i < NROWS * FILT / 4; i += stride) p[i] = z;
}

// pack (idx_i, idx_j, rcut) into one int4 per edge -> 1 LDG.128 in edge kernel
__global__ void pack_meta_kernel(const int* __restrict__ idx_i,
                                 const int* __restrict__ idx_j,
                                 const float* __restrict__ rc) {
    int i = blockIdx.x * blockDim.x + threadIdx.x;
    int stride = gridDim.x * blockDim.x;
    for (; i < P_EDGES; i += stride)
        g_meta[i] = make_int4(idx_i[i], idx_j[i], __float_as_int(rc[i]), 0);
}

// ---------------------------------------------------------------------------
// GEMM (R6-proven scalar version): C[n,oc] = act(sum_k A[n,k]*WT[k,oc] + b[oc])
// A: [nrows,128], WT: [128,128] (k-major). Block tile 64x128, thread tile 8x4.
// ---------------------------------------------------------------------------
template <bool SSP>
__global__ __launch_bounds__(256) void gemm_kernel(const float* __restrict__ A,
                                                   const float* __restrict__ WT,
                                                   const float* __restrict__ bias,
                                                   float* __restrict__ C,
                                                   int nrows) {
    __shared__ float As[64][32];
    __shared__ float Ws[32][128];

    int tid  = threadIdx.x;
    int warp = tid >> 5;
    int lane = tid & 31;
    int gr0  = blockIdx.x * 64;
    int r0   = warp * 8;
    int c0   = lane * 4;

    float4 acc[8];
#pragma unroll
    for (int i = 0; i < 8; i++) acc[i] = make_float4(0.f, 0.f, 0.f, 0.f);

    for (int k0 = 0; k0 < 128; k0 += 32) {
#pragma unroll
        for (int v = 0; v < 2; v++) {
            int fi  = tid + v * 256;   // 0..511
            int row = fi >> 3;
            int kq  = fi & 7;
            int grow = gr0 + row;
            float4 val = make_float4(0.f, 0.f, 0.f, 0.f);
            if (grow < nrows)
                val = *reinterpret_cast<const float4*>(A + (size_t)grow * 128 + k0 + kq * 4);
            *reinterpret_cast<float4*>(&As[row][kq * 4]) = val;
        }
#pragma unroll
        for (int v = 0; v < 4; v++) {
            int fi = tid + v * 256;    // 0..1023
            int kr = fi >> 5;
            int f4 = fi & 31;
            *reinterpret_cast<float4*>(&Ws[kr][f4 * 4]) =
                *reinterpret_cast<const float4*>(WT + (size_t)(k0 + kr) * 128 + f4 * 4);
        }
        __syncthreads();

#pragma unroll
        for (int kk = 0; kk < 32; kk++) {
            float4 bv = *reinterpret_cast<const float4*>(&Ws[kk][c0]);
#pragma unroll
            for (int i = 0; i < 8; i++) {
                float a = As[r0 + i][kk];   // broadcast LDS
                acc[i].x = fmaf(a, bv.x, acc[i].x);
                acc[i].y = fmaf(a, bv.y, acc[i].y);
                acc[i].z = fmaf(a, bv.z, acc[i].z);
                acc[i].w = fmaf(a, bv.w, acc[i].w);
            }
        }
        __syncthreads();
    }

    float4 bb = *reinterpret_cast<const float4*>(bias + c0);
#pragma unroll
    for (int i = 0; i < 8; i++) {
        int grow = gr0 + r0 + i;
        if (grow < nrows) {
            float4 o;
            o.x = acc[i].x + bb.x;
            o.y = acc[i].y + bb.y;
            o.z = acc[i].z + bb.z;
            o.w = acc[i].w + bb.w;
            if (SSP) {
                o.x = sspf(o.x); o.y = sspf(o.y);
                o.z = sspf(o.z); o.w = sspf(o.w);
            }
            *reinterpret_cast<float4*>(C + (size_t)grow * 128 + c0) = o;
        }
    }
}

// ---------------------------------------------------------------------------
// Edge kernel (occupancy-optimized): TWO warps per edge, each warp owns 64
// filters (2 per lane). Weight regs per thread drop 80 -> 40, total footprint
// ~80 regs -> 3 CTAs/SM (24 warps/SM, +50% vs R6's 16). Scalar FFMA math
// (R6-proven; the R7/R9 f32x2 experiment regressed). Both warps of an edge
// live in the same block, so the duplicate f_ij row load hits L1.
// ---------------------------------------------------------------------------
__global__ __launch_bounds__(256, 3) void edge_kernel(const float* __restrict__ f_ij,
                                                      const float* __restrict__ W_filter,
                                                      const float* __restrict__ b_filter) {
    int lane  = threadIdx.x & 31;
    int gwarp = (blockIdx.x * blockDim.x + threadIdx.x) >> 5;
    int nwarp = (gridDim.x * blockDim.x) >> 5;
    int half  = gwarp & 1;                  // which 64-filter half
    int f0    = half * 64 + lane * 2;       // first of this thread's 2 filters

    float w[2][RB];
    float bb[2];
#pragma unroll
    for (int j = 0; j < 2; j++) {
        bb[j] = __ldg(b_filter + f0 + j);
#pragma unroll
        for (int r = 0; r < RB; r++)
            w[j][r] = __ldg(W_filter + (size_t)(f0 + j) * RB + r);
    }

    int npair = nwarp >> 1;
    for (int p = gwarp >> 1; p < P_EDGES; p += npair) {
        int4 mt = __ldg(&g_meta[p]);
        int   ii = mt.x;
        int   ji = mt.y;
        float rc = __int_as_float(mt.z);

        const float4* fr = reinterpret_cast<const float4*>(f_ij + (size_t)p * RB);
        float4 q0 = __ldg(fr + 0);
        float4 q1 = __ldg(fr + 1);
        float4 q2 = __ldg(fr + 2);
        float4 q3 = __ldg(fr + 3);
        float4 q4 = __ldg(fr + 4);
        float fv[RB];
        fv[0]=q0.x; fv[1]=q0.y; fv[2]=q0.z; fv[3]=q0.w;
        fv[4]=q1.x; fv[5]=q1.y; fv[6]=q1.z; fv[7]=q1.w;
        fv[8]=q2.x; fv[9]=q2.y; fv[10]=q2.z; fv[11]=q2.w;
        fv[12]=q3.x; fv[13]=q3.y; fv[14]=q3.z; fv[15]=q3.w;
        fv[16]=q4.x; fv[17]=q4.y; fv[18]=q4.z; fv[19]=q4.w;

        float a0 = bb[0], a1 = bb[1];
#pragma unroll
        for (int r = 0; r < RB; r++) {
            a0 = fmaf(fv[r], w[0][r], a0);
            a1 = fmaf(fv[r], w[1][r], a1);
        }

        float2 hv = *reinterpret_cast<const float2*>(g_h + (size_t)ji * FILT + f0);
        float ox = sspf(a0) * rc * hv.x;
        float oy = sspf(a1) * rc * hv.y;

        float* dst = g_agg + (size_t)ii * FILT + f0;
        asm volatile("red.global.add.v2.f32 [%0], {%1, %2};"
                     :: "l"(dst), "f"(ox), "f"(oy)
                     : "memory");
    }
}

// ---------------------------------------------------------------------------
extern "C" void kernel_launch(void* const* d_in, const int* in_sizes, int n_in,
                              void* d_out, int out_size) {
    int ix = -1, ifij = -1, iwf = -1;
    int i16k[4]; int n16k = 0;       // W_in, W_out (16384 elems each)
    int i1m6[4]; int n1m6 = 0;       // idx_i, idx_j, rcut_ij (1.6M each)
    int i128[4]; int n128 = 0;       // b_in, b_filter, b_out (128 each)

    for (int i = 0; i < n_in; i++) {
        long s = in_sizes[i];
        if      (s == 6400000)  ix   = i;              // x [1,50000,128]
        else if (s == 32000000) ifij = i;              // f_ij [P,20]
        else if (s == 2560)     iwf  = i;              // W_filter [128,20]
        else if (s == 16384)  { if (n16k < 4) i16k[n16k++] = i; }
        else if (s == 1600000){ if (n1m6 < 4) i1m6[n1m6++] = i; }
        else if (s == 128)    { if (n128 < 4) i128[n128++] = i; }
    }

    const float* x        = (const float*)d_in[ix];
    const float* f_ij     = (const float*)d_in[ifij];
    const float* W_filter = (const float*)d_in[iwf];
    const int*   idx_i    = (const int*)d_in[i1m6[0]];
    const int*   idx_j    = (const int*)d_in[i1m6[1]];
    const float* rcut_ij  = (const float*)d_in[i1m6[2]];
    const float* W_in     = (const float*)d_in[i16k[0]];
    const float* W_out    = (const float*)d_in[i16k[1]];
    bool sorted_keys = (i128[0] < ifij);
    const float* b_in     = (const float*)d_in[sorted_keys ? i128[1] : i128[0]];
    const float* b_filter = (const float*)d_in[sorted_keys ? i128[0] : i128[1]];
    const float* b_out    = (const float*)d_in[i128[2]];

    float* out = (float*)d_out;

    // Resolve REAL device addresses of scratch globals (host query, no alloc,
    // executes immediately — safe under graph capture).
    void *p_h, *p_agg, *p_WinT, *p_WoutT;
    cudaGetSymbolAddress(&p_h,     g_h);
    cudaGetSymbolAddress(&p_agg,   g_agg);
    cudaGetSymbolAddress(&p_WinT,  g_WinT);
    cudaGetSymbolAddress(&p_WoutT, g_WoutT);
    float* dev_h     = (float*)p_h;
    float* dev_agg   = (float*)p_agg;
    float* dev_WinT  = (float*)p_WinT;
    float* dev_WoutT = (float*)p_WoutT;

    // 1. transpose weights (k-major for GEMM) + pack edge metadata
    transpose2_kernel<<<64, 256>>>(W_in, W_out);
    pack_meta_kernel<<<1024, 256>>>(idx_i, idx_j, rcut_ij);

    // 2. h = x @ W_in^T + b_in
    gemm_kernel<false><<<(NROWS + 63) / 64, 256>>>(x, dev_WinT, b_in, dev_h, NROWS);

    // 3. zero accumulator
    zero_agg_kernel<<<1024, 256>>>();

    // 4. fused filter-net + gather + scatter-add (2 warps/edge, 3 CTA/SM)
    edge_kernel<<<1332, 256>>>(f_ij, W_filter, b_filter);

    // 5. out = ssp(agg @ W_out^T + b_out)
    gemm_kernel<true><<<(NROWS + 63) / 64, 256>>>(dev_agg, dev_WoutT, b_out, out, NROWS);
}

// round 11
// speedup vs baseline: 2.0344x; 1.4372x over previous
#include <cuda_runtime.h>
#include <cstdint>

#define NROWS 50000
#define DIM   128
#define FILT  128
#define RB    20
#define P_EDGES 1600000
#define NTILES (P_EDGES / 64)   // 25000

// scratch (device globals: no allocation allowed)
__device__ float g_h[NROWS * FILT];
__device__ float g_agg[NROWS * FILT];
__device__ float g_WinT[DIM * FILT];   // [k=d][oc=f]
__device__ float g_WoutT[FILT * DIM];  // [k=f][oc=d]
__device__ int4  g_meta[P_EDGES];      // (idx_i, idx_j, bitcast(rcut), 0)

__device__ __forceinline__ float sspf(float x) {
    // softplus(x) - ln2, fast path. For x>15, log1p(exp(x)) ~= x (err < 3e-7)
    float r = __logf(1.0f + __expf(x));
    r = (x > 15.0f) ? x : r;
    return r - 0.69314718055994530942f;
}

// ---------------------------------------------------------------------------
// transpose both 128x128 weight matrices into [k][oc] layout
// ---------------------------------------------------------------------------
__global__ void transpose2_kernel(const float* __restrict__ Win,
                                  const float* __restrict__ Wout) {
    int i = blockIdx.x * blockDim.x + threadIdx.x;
    if (i < 128 * 128) {
        int oc = i >> 7, k = i & 127;
        g_WinT[k * 128 + oc]  = Win[oc * 128 + k];
        g_WoutT[k * 128 + oc] = Wout[oc * 128 + k];
    }
}

__global__ void zero_agg_kernel() {
    int i = blockIdx.x * blockDim.x + threadIdx.x;
    int stride = gridDim.x * blockDim.x;
    float4 z = make_float4(0.f, 0.f, 0.f, 0.f);
    float4* p = reinterpret_cast<float4*>(g_agg);
    for (; i < NROWS * FILT / 4; i += stride) p[i] = z;
}

// pack (idx_i, idx_j, rcut) into one int4 per edge
__global__ void pack_meta_kernel(const int* __restrict__ idx_i,
                                 const int* __restrict__ idx_j,
                                 const float* __restrict__ rc) {
    int i = blockIdx.x * blockDim.x + threadIdx.x;
    int stride = gridDim.x * blockDim.x;
    for (; i < P_EDGES; i += stride)
        g_meta[i] = make_int4(idx_i[i], idx_j[i], __float_as_int(rc[i]), 0);
}

// ---------------------------------------------------------------------------
// GEMM (R6-proven scalar version): C[n,oc] = act(sum_k A[n,k]*WT[k,oc] + b[oc])
// A: [nrows,128], WT: [128,128] (k-major). Block tile 64x128, thread tile 8x4.
// ---------------------------------------------------------------------------
template <bool SSP>
__global__ __launch_bounds__(256) void gemm_kernel(const float* __restrict__ A,
                                                   const float* __restrict__ WT,
                                                   const float* __restrict__ bias,
                                                   float* __restrict__ C,
                                                   int nrows) {
    __shared__ float As[64][32];
    __shared__ float Ws[32][128];

    int tid  = threadIdx.x;
    int warp = tid >> 5;
    int lane = tid & 31;
    int gr0  = blockIdx.x * 64;
    int r0   = warp * 8;
    int c0   = lane * 4;

    float4 acc[8];
#pragma unroll
    for (int i = 0; i < 8; i++) acc[i] = make_float4(0.f, 0.f, 0.f, 0.f);

    for (int k0 = 0; k0 < 128; k0 += 32) {
#pragma unroll
        for (int v = 0; v < 2; v++) {
            int fi  = tid + v * 256;   // 0..511
            int row = fi >> 3;
            int kq  = fi & 7;
            int grow = gr0 + row;
            float4 val = make_float4(0.f, 0.f, 0.f, 0.f);
            if (grow < nrows)
                val = *reinterpret_cast<const float4*>(A + (size_t)grow * 128 + k0 + kq * 4);
            *reinterpret_cast<float4*>(&As[row][kq * 4]) = val;
        }
#pragma unroll
        for (int v = 0; v < 4; v++) {
            int fi = tid + v * 256;    // 0..1023
            int kr = fi >> 5;
            int f4 = fi & 31;
            *reinterpret_cast<float4*>(&Ws[kr][f4 * 4]) =
                *reinterpret_cast<const float4*>(WT + (size_t)(k0 + kr) * 128 + f4 * 4);
        }
        __syncthreads();

#pragma unroll
        for (int kk = 0; kk < 32; kk++) {
            float4 bv = *reinterpret_cast<const float4*>(&Ws[kk][c0]);
#pragma unroll
            for (int i = 0; i < 8; i++) {
                float a = As[r0 + i][kk];   // broadcast LDS
                acc[i].x = fmaf(a, bv.x, acc[i].x);
                acc[i].y = fmaf(a, bv.y, acc[i].y);
                acc[i].z = fmaf(a, bv.z, acc[i].z);
                acc[i].w = fmaf(a, bv.w, acc[i].w);
            }
        }
        __syncthreads();
    }

    float4 bb = *reinterpret_cast<const float4*>(bias + c0);
#pragma unroll
    for (int i = 0; i < 8; i++) {
        int grow = gr0 + r0 + i;
        if (grow < nrows) {
            float4 o;
            o.x = acc[i].x + bb.x;
            o.y = acc[i].y + bb.y;
            o.z = acc[i].z + bb.z;
            o.w = acc[i].w + bb.w;
            if (SSP) {
                o.x = sspf(o.x); o.y = sspf(o.y);
                o.z = sspf(o.z); o.w = sspf(o.w);
            }
            *reinterpret_cast<float4*>(C + (size_t)grow * 128 + c0) = o;
        }
    }
}

// ---------------------------------------------------------------------------
// Edge stage as a tiled GEMM (mirrors gemm_kernel's proven mainloop shape):
// block tile = 64 edges x 128 filters, K=20 in one pass.
//   Wij[64x128] = Fs[64x20] @ Wt[20x128]          (pure LDS+FFMA mainloop)
//   epilogue: ssp(Wij+b) * rcut * h[idx_j]  -->  red.v4 into agg[idx_i]
// The gather/atomic latency lives only in the epilogue and overlaps with
// other blocks' mainloops (25000 independent blocks). Warp lanes span all
// 128 filters of one edge row -> gather LDG.128 and red.v4 are coalesced
// 512B row accesses (L2-resident: h/agg tables are 25.6MB each).
// ---------------------------------------------------------------------------
__global__ __launch_bounds__(256) void edge_gemm_kernel(const float* __restrict__ f_ij,
                                                        const float* __restrict__ W_filter,
                                                        const float* __restrict__ b_filter) {
    __shared__ float Fs[64 * RB];        // 5 KB  f_ij tile
    __shared__ float Wt[RB][FILT];       // 10 KB W_filter^T
    __shared__ int4  Ms[64];             // 1 KB  meta tile
    __shared__ float Bs[FILT];           // 0.5 KB bias

    int tid  = threadIdx.x;
    int warp = tid >> 5;
    int lane = tid & 31;
    int r0   = warp * 8;                 // 8 edge rows per warp
    int c0   = lane * 4;                 // 4 filters per lane

    // stage W^T (transpose on the fly) + bias
#pragma unroll
    for (int v = 0; v < 10; v++) {
        int idx = tid + v * 256;         // 0..2559
        int f = idx / RB, kk = idx % RB;
        Wt[kk][f] = W_filter[idx];
    }
    if (tid < FILT) Bs[tid] = b_filter[tid];

    // stage this tile's meta + f_ij (fully coalesced: 1280 contiguous floats)
    int e0 = blockIdx.x * 64;
    if (tid < 64) Ms[tid] = __ldg(&g_meta[e0 + tid]);
    const float* fb = f_ij + (size_t)e0 * RB;
#pragma unroll
    for (int v = 0; v < 5; v++)
        Fs[tid + v * 256] = __ldg(fb + tid + v * 256);
    __syncthreads();

    // mainloop: 640 FFMA per thread, K=20 fully unrolled
    float4 acc[8];
#pragma unroll
    for (int i = 0; i < 8; i++) acc[i] = make_float4(0.f, 0.f, 0.f, 0.f);

#pragma unroll
    for (int kk = 0; kk < RB; kk++) {
        float4 bv = *reinterpret_cast<const float4*>(&Wt[kk][c0]);
#pragma unroll
        for (int i = 0; i < 8; i++) {
            float a = Fs[(r0 + i) * RB + kk];   // warp-broadcast LDS
            acc[i].x = fmaf(a, bv.x, acc[i].x);
            acc[i].y = fmaf(a, bv.y, acc[i].y);
            acc[i].z = fmaf(a, bv.z, acc[i].z);
            acc[i].w = fmaf(a, bv.w, acc[i].w);
        }
    }

    // epilogue: ssp, cutoff, gather, scatter-add
    float4 bb = *reinterpret_cast<const float4*>(&Bs[c0]);
#pragma unroll
    for (int i = 0; i < 8; i++) {
        int4  mt = Ms[r0 + i];
        float rc = __int_as_float(mt.z);

        float4 hv = *reinterpret_cast<const float4*>(g_h + (size_t)mt.y * FILT + c0);

        float ox = sspf(acc[i].x + bb.x) * rc * hv.x;
        float oy = sspf(acc[i].y + bb.y) * rc * hv.y;
        float oz = sspf(acc[i].z + bb.z) * rc * hv.z;
        float ow = sspf(acc[i].w + bb.w) * rc * hv.w;

        float* dst = g_agg + (size_t)mt.x * FILT + c0;
        asm volatile("red.global.add.v4.f32 [%0], {%1, %2, %3, %4};"
                     :: "l"(dst), "f"(ox), "f"(oy), "f"(oz), "f"(ow)
                     : "memory");
    }
}

// ---------------------------------------------------------------------------
extern "C" void kernel_launch(void* const* d_in, const int* in_sizes, int n_in,
                              void* d_out, int out_size) {
    int ix = -1, ifij = -1, iwf = -1;
    int i16k[4]; int n16k = 0;       // W_in, W_out (16384 elems each)
    int i1m6[4]; int n1m6 = 0;       // idx_i, idx_j, rcut_ij (1.6M each)
    int i128[4]; int n128 = 0;       // b_in, b_filter, b_out (128 each)

    for (int i = 0; i < n_in; i++) {
        long s = in_sizes[i];
        if      (s == 6400000)  ix   = i;              // x [1,50000,128]
        else if (s == 32000000) ifij = i;              // f_ij [P,20]
        else if (s == 2560)     iwf  = i;              // W_filter [128,20]
        else if (s == 16384)  { if (n16k < 4) i16k[n16k++] = i; }
        else if (s == 1600000){ if (n1m6 < 4) i1m6[n1m6++] = i; }
        else if (s == 128)    { if (n128 < 4) i128[n128++] = i; }
    }

    const float* x        = (const float*)d_in[ix];
    const float* f_ij     = (const float*)d_in[ifij];
    const float* W_filter = (const float*)d_in[iwf];
    const int*   idx_i    = (const int*)d_in[i1m6[0]];
    const int*   idx_j    = (const int*)d_in[i1m6[1]];
    const float* rcut_ij  = (const float*)d_in[i1m6[2]];
    const float* W_in     = (const float*)d_in[i16k[0]];
    const float* W_out    = (const float*)d_in[i16k[1]];
    bool sorted_keys = (i128[0] < ifij);
    const float* b_in     = (const float*)d_in[sorted_keys ? i128[1] : i128[0]];
    const float* b_filter = (const float*)d_in[sorted_keys ? i128[0] : i128[1]];
    const float* b_out    = (const float*)d_in[i128[2]];

    float* out = (float*)d_out;

    // Resolve REAL device addresses of scratch globals (host query, no alloc,
    // executes immediately — safe under graph capture).
    void *p_h, *p_agg, *p_WinT, *p_WoutT;
    cudaGetSymbolAddress(&p_h,     g_h);
    cudaGetSymbolAddress(&p_agg,   g_agg);
    cudaGetSymbolAddress(&p_WinT,  g_WinT);
    cudaGetSymbolAddress(&p_WoutT, g_WoutT);
    float* dev_h     = (float*)p_h;
    float* dev_agg   = (float*)p_agg;
    float* dev_WinT  = (float*)p_WinT;
    float* dev_WoutT = (float*)p_WoutT;

    // 1. transpose weights (k-major for GEMM) + pack edge metadata
    transpose2_kernel<<<64, 256>>>(W_in, W_out);
    pack_meta_kernel<<<1024, 256>>>(idx_i, idx_j, rcut_ij);

    // 2. h = x @ W_in^T + b_in
    gemm_kernel<false><<<(NROWS + 63) / 64, 256>>>(x, dev_WinT, b_in, dev_h, NROWS);

    // 3. zero accumulator
    zero_agg_kernel<<<1024, 256>>>();

    // 4. edge stage as tiled GEMM + fused epilogue (gather/ssp/scatter)
    edge_gemm_kernel<<<NTILES, 256>>>(f_ij, W_filter, b_filter);

    // 5. out = ssp(agg @ W_out^T + b_out)
    gemm_kernel<true><<<(NROWS + 63) / 64, 256>>>(dev_agg, dev_WoutT, b_out, out, NROWS);
}

// round 13
// speedup vs baseline: 2.3125x; 1.1367x over previous
#include <cuda_runtime.h>
#include <cstdint>

#define NROWS 50000
#define DIM   128
#define FILT  128
#define RB    20
#define P_EDGES 1600000
#define NTILES (P_EDGES / 64)     // 25000
#define TPB_TILES 10              // tiles per block
#define EDGE_GRID (NTILES / TPB_TILES)  // 2500

// scratch (device globals: no allocation allowed)
__device__ float g_h[NROWS * FILT];
__device__ float g_agg[NROWS * FILT];
__device__ float g_WinT[DIM * FILT];   // [k=d][oc=f]
__device__ float g_WoutT[FILT * DIM];  // [k=f][oc=d]
__device__ int4  g_meta[P_EDGES];      // (idx_i, idx_j, bitcast(rcut), 0)

__device__ __forceinline__ float sspf(float x) {
    // softplus(x) - ln2, fast path. For x>15, log1p(exp(x)) ~= x (err < 3e-7)
    float r = __logf(1.0f + __expf(x));
    r = (x > 15.0f) ? x : r;
    return r - 0.69314718055994530942f;
}

// ---------------------------------------------------------------------------
// Fused prelude: weight transposes + meta pack + agg zero in one launch.
// grid-stride covers the largest job (P_EDGES).
// ---------------------------------------------------------------------------
__global__ void prelude_kernel(const float* __restrict__ Win,
                               const float* __restrict__ Wout,
                               const int* __restrict__ idx_i,
                               const int* __restrict__ idx_j,
                               const float* __restrict__ rc) {
    int i = blockIdx.x * blockDim.x + threadIdx.x;
    int stride = gridDim.x * blockDim.x;

    if (i < 128 * 128) {
        int oc = i >> 7, k = i & 127;
        g_WinT[k * 128 + oc]  = Win[oc * 128 + k];
        g_WoutT[k * 128 + oc] = Wout[oc * 128 + k];
    }

    float4 z = make_float4(0.f, 0.f, 0.f, 0.f);
    float4* p = reinterpret_cast<float4*>(g_agg);
    for (int t = i; t < NROWS * FILT / 4; t += stride) p[t] = z;

    for (int t = i; t < P_EDGES; t += stride)
        g_meta[t] = make_int4(idx_i[t], idx_j[t], __float_as_int(rc[t]), 0);
}

// ---------------------------------------------------------------------------
// GEMM (R6-proven scalar version): C[n,oc] = act(sum_k A[n,k]*WT[k,oc] + b[oc])
// A: [nrows,128], WT: [128,128] (k-major). Block tile 64x128, thread tile 8x4.
// ---------------------------------------------------------------------------
template <bool SSP>
__global__ __launch_bounds__(256) void gemm_kernel(const float* __restrict__ A,
                                                   const float* __restrict__ WT,
                                                   const float* __restrict__ bias,
                                                   float* __restrict__ C,
                                                   int nrows) {
    __shared__ float As[64][32];
    __shared__ float Ws[32][128];

    int tid  = threadIdx.x;
    int warp = tid >> 5;
    int lane = tid & 31;
    int gr0  = blockIdx.x * 64;
    int r0   = warp * 8;
    int c0   = lane * 4;

    float4 acc[8];
#pragma unroll
    for (int i = 0; i < 8; i++) acc[i] = make_float4(0.f, 0.f, 0.f, 0.f);

    for (int k0 = 0; k0 < 128; k0 += 32) {
#pragma unroll
        for (int v = 0; v < 2; v++) {
            int fi  = tid + v * 256;   // 0..511
            int row = fi >> 3;
            int kq  = fi & 7;
            int grow = gr0 + row;
            float4 val = make_float4(0.f, 0.f, 0.f, 0.f);
            if (grow < nrows)
                val = *reinterpret_cast<const float4*>(A + (size_t)grow * 128 + k0 + kq * 4);
            *reinterpret_cast<float4*>(&As[row][kq * 4]) = val;
        }
#pragma unroll
        for (int v = 0; v < 4; v++) {
            int fi = tid + v * 256;    // 0..1023
            int kr = fi >> 5;
            int f4 = fi & 31;
            *reinterpret_cast<float4*>(&Ws[kr][f4 * 4]) =
                *reinterpret_cast<const float4*>(WT + (size_t)(k0 + kr) * 128 + f4 * 4);
        }
        __syncthreads();

#pragma unroll
        for (int kk = 0; kk < 32; kk++) {
            float4 bv = *reinterpret_cast<const float4*>(&Ws[kk][c0]);
#pragma unroll
            for (int i = 0; i < 8; i++) {
                float a = As[r0 + i][kk];   // broadcast LDS
                acc[i].x = fmaf(a, bv.x, acc[i].x);
                acc[i].y = fmaf(a, bv.y, acc[i].y);
                acc[i].z = fmaf(a, bv.z, acc[i].z);
                acc[i].w = fmaf(a, bv.w, acc[i].w);
            }
        }
        __syncthreads();
    }

    float4 bb = *reinterpret_cast<const float4*>(bias + c0);
#pragma unroll
    for (int i = 0; i < 8; i++) {
        int grow = gr0 + r0 + i;
        if (grow < nrows) {
            float4 o;
            o.x = acc[i].x + bb.x;
            o.y = acc[i].y + bb.y;
            o.z = acc[i].z + bb.z;
            o.w = acc[i].w + bb.w;
            if (SSP) {
                o.x = sspf(o.x); o.y = sspf(o.y);
                o.z = sspf(o.z); o.w = sspf(o.w);
            }
            *reinterpret_cast<float4*>(C + (size_t)grow * 128 + c0) = o;
        }
    }
}

// ---------------------------------------------------------------------------
// Edge stage as tiled GEMM, v2:
//  - each block owns TPB_TILES consecutive 64-edge tiles; Wt/Bs staged ONCE
//  - next tile's Fs/Ms prefetched into registers before the mainloop,
//    stored to smem after the epilogue (LDG latency hidden under FFMAs)
//  - mainloop reads f_ij two k-values per LDS.64 (warp-uniform broadcast)
//  - bias pre-loaded into accumulators
// Epilogue per edge row: ssp(acc)*rcut*h[idx_j] -> red.v4 into agg[idx_i];
// both are coalesced 512B row accesses on L2-resident tables.
// ---------------------------------------------------------------------------
__global__ __launch_bounds__(256) void edge_gemm_kernel(const float* __restrict__ f_ij,
                                                        const float* __restrict__ W_filter,
                                                        const float* __restrict__ b_filter) {
    __shared__ float Fs[64 * RB];        // 5 KB  f_ij tile
    __shared__ float Wt[RB][FILT];       // 10 KB W_filter^T
    __shared__ int4  Ms[64];             // 1 KB  meta tile
    __shared__ float Bs[FILT];           // 0.5 KB bias

    int tid  = threadIdx.x;
    int warp = tid >> 5;
    int lane = tid & 31;
    int r0   = warp * 8;                 // 8 edge rows per warp
    int c0   = lane * 4;                 // 4 filters per lane

    // stage W^T (transpose on the fly) + bias — once per block
#pragma unroll
    for (int v = 0; v < 10; v++) {
        int idx = tid + v * 256;         // 0..2559
        int f = idx / RB, kk = idx % RB;
        Wt[kk][f] = W_filter[idx];
    }
    if (tid < FILT) Bs[tid] = b_filter[tid];

    int t0 = blockIdx.x * TPB_TILES;

    // stage first tile
    {
        int e0 = t0 * 64;
        if (tid < 64) Ms[tid] = __ldg(&g_meta[e0 + tid]);
        const float* fb = f_ij + (size_t)e0 * RB;
#pragma unroll
        for (int v = 0; v < 5; v++)
            Fs[tid + v * 256] = __ldg(fb + tid + v * 256);
    }
    __syncthreads();

    float4 bb = *reinterpret_cast<const float4*>(&Bs[c0]);

    for (int t = 0; t < TPB_TILES; t++) {
        // prefetch next tile into registers (hidden under mainloop)
        float pf[5];
        int4  pm;
        if (t + 1 < TPB_TILES) {
            int e1 = (t0 + t + 1) * 64;
            const float* fb = f_ij + (size_t)e1 * RB;
#pragma unroll
            for (int v = 0; v < 5; v++) pf[v] = __ldg(fb + tid + v * 256);
            if (tid < 64) pm = __ldg(&g_meta[e1 + tid]);
        }

        // mainloop: 640 FFMA, a-values via LDS.64 pairs (10 k-pairs)
        float4 acc[8];
#pragma unroll
        for (int i = 0; i < 8; i++) acc[i] = bb;

#pragma unroll
        for (int kp = 0; kp < 10; kp++) {
            float4 bv0 = *reinterpret_cast<const float4*>(&Wt[2 * kp][c0]);
            float4 bv1 = *reinterpret_cast<const float4*>(&Wt[2 * kp + 1][c0]);
#pragma unroll
            for (int i = 0; i < 8; i++) {
                float2 a2 = *reinterpret_cast<const float2*>(&Fs[(r0 + i) * RB + 2 * kp]);
                acc[i].x = fmaf(a2.x, bv0.x, acc[i].x);
                acc[i].y = fmaf(a2.x, bv0.y, acc[i].y);
                acc[i].z = fmaf(a2.x, bv0.z, acc[i].z);
                acc[i].w = fmaf(a2.x, bv0.w, acc[i].w);
                acc[i].x = fmaf(a2.y, bv1.x, acc[i].x);
                acc[i].y = fmaf(a2.y, bv1.y, acc[i].y);
                acc[i].z = fmaf(a2.y, bv1.z, acc[i].z);
                acc[i].w = fmaf(a2.y, bv1.w, acc[i].w);
            }
        }

        // epilogue: ssp, cutoff, gather, scatter-add
#pragma unroll
        for (int i = 0; i < 8; i++) {
            int4  mt = Ms[r0 + i];
            float rc = __int_as_float(mt.z);

            float4 hv = *reinterpret_cast<const float4*>(g_h + (size_t)mt.y * FILT + c0);

            float ox = sspf(acc[i].x) * rc * hv.x;
            float oy = sspf(acc[i].y) * rc * hv.y;
            float oz = sspf(acc[i].z) * rc * hv.z;
            float ow = sspf(acc[i].w) * rc * hv.w;

            float* dst = g_agg + (size_t)mt.x * FILT + c0;
            asm volatile("red.global.add.v4.f32 [%0], {%1, %2, %3, %4};"
                         :: "l"(dst), "f"(ox), "f"(oy), "f"(oz), "f"(ow)
                         : "memory");
        }

        if (t + 1 < TPB_TILES) {
            __syncthreads();   // all reads of current tile done
#pragma unroll
            for (int v = 0; v < 5; v++) Fs[tid + v * 256] = pf[v];
            if (tid < 64) Ms[tid] = pm;
            __syncthreads();   // next tile visible
        }
    }
}

// ---------------------------------------------------------------------------
extern "C" void kernel_launch(void* const* d_in, const int* in_sizes, int n_in,
                              void* d_out, int out_size) {
    int ix = -1, ifij = -1, iwf = -1;
    int i16k[4]; int n16k = 0;       // W_in, W_out (16384 elems each)
    int i1m6[4]; int n1m6 = 0;       // idx_i, idx_j, rcut_ij (1.6M each)
    int i128[4]; int n128 = 0;       // b_in, b_filter, b_out (128 each)

    for (int i = 0; i < n_in; i++) {
        long s = in_sizes[i];
        if      (s == 6400000)  ix   = i;              // x [1,50000,128]
        else if (s == 32000000) ifij = i;              // f_ij [P,20]
        else if (s == 2560)     iwf  = i;              // W_filter [128,20]
        else if (s == 16384)  { if (n16k < 4) i16k[n16k++] = i; }
        else if (s == 1600000){ if (n1m6 < 4) i1m6[n1m6++] = i; }
        else if (s == 128)    { if (n128 < 4) i128[n128++] = i; }
    }

    const float* x        = (const float*)d_in[ix];
    const float* f_ij     = (const float*)d_in[ifij];
    const float* W_filter = (const float*)d_in[iwf];
    const int*   idx_i    = (const int*)d_in[i1m6[0]];
    const int*   idx_j    = (const int*)d_in[i1m6[1]];
    const float* rcut_ij  = (const float*)d_in[i1m6[2]];
    const float* W_in     = (const float*)d_in[i16k[0]];
    const float* W_out    = (const float*)d_in[i16k[1]];
    bool sorted_keys = (i128[0] < ifij);
    const float* b_in     = (const float*)d_in[sorted_keys ? i128[1] : i128[0]];
    const float* b_filter = (const float*)d_in[sorted_keys ? i128[0] : i128[1]];
    const float* b_out    = (const float*)d_in[i128[2]];

    float* out = (float*)d_out;

    // Resolve REAL device addresses of scratch globals (host query, no alloc,
    // executes immediately — safe under graph capture).
    void *p_h, *p_agg, *p_WinT, *p_WoutT;
    cudaGetSymbolAddress(&p_h,     g_h);
    cudaGetSymbolAddress(&p_agg,   g_agg);
    cudaGetSymbolAddress(&p_WinT,  g_WinT);
    cudaGetSymbolAddress(&p_WoutT, g_WoutT);
    float* dev_h     = (float*)p_h;
    float* dev_agg   = (float*)p_agg;
    float* dev_WinT  = (float*)p_WinT;
    float* dev_WoutT = (float*)p_WoutT;

    // 1. fused prelude: transposes + meta pack + agg zero
    prelude_kernel<<<2048, 256>>>(W_in, W_out, idx_i, idx_j, rcut_ij);

    // 2. h = x @ W_in^T + b_in
    gemm_kernel<false><<<(NROWS + 63) / 64, 256>>>(x, dev_WinT, b_in, dev_h, NROWS);

    // 3. edge stage as tiled GEMM + fused epilogue (gather/ssp/scatter)
    edge_gemm_kernel<<<EDGE_GRID, 256>>>(f_ij, W_filter, b_filter);

    // 4. out = ssp(agg @ W_out^T + b_out)
    gemm_kernel<true><<<(NROWS + 63) / 64, 256>>>(dev_agg, dev_WoutT, b_out, out, NROWS);
}